// round 5
// baseline (speedup 1.0000x reference)
#include <cuda_runtime.h>
#include <cstdint>
#include <cstddef>

#define HH 512
#define WW 512
#define NIMG 16
#define NPIX (HH*WW)
#define NT   ((size_t)NIMG*NPIX)
#define OD 2045

// ---------------- device scratch (static; no allocations) ----------------
// SoA activation planes: 3 words (12 bytes = 12 channels) per pixel, one plane per word.
__device__ int g_pA[3*NT];   // ping
__device__ int g_pB[3*NT];   // pong
__device__ int   g_w0p4[80];      // conv0: [dy5][oc16] packed (w[dx0..3]-128)
__device__ int   g_w0p1[80];      // conv0: [dy5][oc16] scalar (w[dx4]-128)
__device__ int   g_w1p[48];       // conv1: [oc12][4 words of ic16]
__device__ int   g_w35p[4][432];  // layers 2..5: [(o*9+t)*4 + j], j=3 pad
__device__ int   g_w6p[48];       // conv6: [oc16][3 words of ic12]
// deconv weights, channel-paired, valid taps only:
// [j=cpair(8)][seq(81), padded to 82] -> float2 (c=2j, c=2j+1)
__device__ __align__(16) float2 g_pw2[8*82];

__device__ __forceinline__ int dp4a_us(unsigned a, int b, int c)
{
    int r;
    asm("dp4a.u32.s32 %0, %1, %2, %3;" : "=r"(r) : "r"(a), "r"(b), "r"(c));
    return r;
}

// ---------------- weight packing ----------------
__global__ void pack_weights_kernel(const int* __restrict__ w0, const int* __restrict__ w1,
                                    const int* __restrict__ w2, const int* __restrict__ w3,
                                    const int* __restrict__ w4, const int* __restrict__ w5,
                                    const int* __restrict__ w6, const float* __restrict__ wt)
{
    int tid = threadIdx.x;
    // conv0: (16,1,5,5) -> row-packed dp4a form
    for (int idx = tid; idx < 80; idx += blockDim.x) {
        int dy = idx / 16, o = idx % 16;
        unsigned r = 0;
        for (int b = 0; b < 4; b++) {
            int v = w0[o*25 + dy*5 + b] - 128;
            r |= ((unsigned)(v & 255)) << (8*b);
        }
        g_w0p4[idx] = (int)r;
        g_w0p1[idx] = w0[o*25 + dy*5 + 4] - 128;
    }
    for (int idx = tid; idx < 48; idx += blockDim.x) {
        int o = idx / 4, j = idx % 4;
        unsigned r = 0;
        for (int b = 0; b < 4; b++) {
            int v = w1[o*16 + j*4 + b] - 128;
            r |= ((unsigned)(v & 255)) << (8*b);
        }
        g_w1p[idx] = (int)r;
    }
    // 3x3 layers: [(o*9+t)*4 + j], j<3 packed bytes over ic, j==3 zero pad
    for (int l = 0; l < 4; l++) {
        const int* ws = (l == 0) ? w2 : (l == 1) ? w3 : (l == 2) ? w4 : w5;
        for (int idx = tid; idx < 432; idx += blockDim.x) {
            int o = idx / 36;
            int rem = idx % 36;
            int t = rem / 4, j = rem % 4;
            unsigned r = 0;
            if (j < 3) {
                for (int b = 0; b < 4; b++) {
                    int i = j*4 + b;
                    int v = ws[(o*12 + i)*9 + t] - 128;
                    r |= ((unsigned)(v & 255)) << (8*b);
                }
            }
            g_w35p[l][idx] = (int)r;
        }
    }
    for (int idx = tid; idx < 48; idx += blockDim.x) {
        int o = idx / 3, j = idx % 3;
        unsigned r = 0;
        for (int b = 0; b < 4; b++) {
            int v = w6[o*12 + j*4 + b] - 128;
            r |= ((unsigned)(v & 255)) << (8*b);
        }
        g_w6p[idx] = (int)r;
    }
    // deconv phase weights (valid taps only; order must match deconv_kernel):
    // out(ry,rx) at grid G uses input (G+dy,G+dx) with a = 4*dy + 4 - ry,
    // b = 4*dx + 4 - rx; valid iff a,b in [0,8]; k[0][c][a][b] = wt[c][0][8-a][8-b].
    if (tid < 8) {
        int j = tid;
        int seq = 0;
        for (int ry = 0; ry < 4; ry++)
        for (int rx = 0; rx < 4; rx++)
        for (int dy = -1; dy <= 1; dy++) {
            if (dy < 0 && ry != 0) continue;
            for (int dx = -1; dx <= 1; dx++) {
                if (dx < 0 && rx != 0) continue;
                int a = 4*dy + 4 - ry;
                int b = 4*dx + 4 - rx;
                float v0 = wt[(2*j + 0)*81 + (8 - a)*9 + (8 - b)];
                float v1 = wt[(2*j + 1)*81 + (8 - a)*9 + (8 - b)];
                g_pw2[j*82 + seq] = make_float2(v0, v1);
                seq++;
            }
        }
    }
}

__device__ __forceinline__ int requant(int acc, float M)
{
    float q = rintf((float)acc * M);     // half-to-even, matches jnp.round
    q = fminf(fmaxf(q, 0.f), 127.f);     // clamp[-127,127] ∘ relu == clamp[0,127]
    return (int)q;
}

// ---------------- fused quant + conv0(k5,1->16) + conv1(1x1,16->12) ----------------
__global__ __launch_bounds__(256) void conv01_kernel(const float* __restrict__ x,
                                                     const int* __restrict__ b0,
                                                     const int* __restrict__ b1,
                                                     float M0, float M1)
{
    __shared__ unsigned tilew[12][10];   // 12 rows x 40 bytes of quantized input
    __shared__ int w0p4sm[80];
    __shared__ int w0p1sm[80];
    __shared__ int w1sm[48];
    __shared__ int b0sm[16];
    __shared__ int b1sm[12];
    int tid = threadIdx.y*32 + threadIdx.x;
    if (tid < 80)  w0p4sm[tid] = g_w0p4[tid];
    if (tid >= 80 && tid < 160) w0p1sm[tid - 80] = g_w0p1[tid - 80];
    if (tid >= 160 && tid < 208) w1sm[tid - 160] = g_w1p[tid - 160];
    if (tid >= 208 && tid < 224) b0sm[tid - 208] = b0[tid - 208];
    if (tid >= 224 && tid < 236) b1sm[tid - 224] = b1[tid - 224];

    int n = blockIdx.z;
    int x0 = blockIdx.x*32, y0 = blockIdx.y*8;
    const float* in = x + (size_t)n*NPIX;
    const float in_s = (float)(1.0/255.0);
    if (tid < 120) {
        int iy = tid / 10, iw = tid % 10;
        int gy = y0 + iy - 2;
        unsigned wv = 0;
        for (int b = 0; b < 4; b++) {
            int gx = x0 + iw*4 + b - 2;
            unsigned char v = 0;
            if (gy >= 0 && gy < HH && gx >= 0 && gx < WW) {
                float q = rintf(__fdiv_rn(in[gy*WW + gx], in_s));
                q = fminf(fmaxf(q, 0.f), 255.f);
                v = (unsigned char)(int)q;
            }
            wv |= ((unsigned)v) << (8*b);
        }
        tilew[iy][iw] = wv;
    }
    __syncthreads();

    int tx = threadIdx.x, ty = threadIdx.y;
    int acc[16];
#pragma unroll
    for (int c = 0; c < 16; c++) acc[c] = b0sm[c];
    int wofs = tx >> 2, sh = (tx & 3)*8;
#pragma unroll
    for (int dy = 0; dy < 5; dy++) {
        unsigned wlo = tilew[ty + dy][wofs];
        unsigned whi = tilew[ty + dy][wofs + 1];
        unsigned wnx = tilew[ty + dy][wofs + 2];
        unsigned b03 = __funnelshift_r(wlo, whi, sh);
        int b4 = (int)(__funnelshift_r(whi, wnx, sh) & 0xFFu);
#pragma unroll
        for (int o = 0; o < 16; o++) {
            acc[o] = dp4a_us(b03, w0p4sm[dy*16 + o], acc[o]);
            acc[o] += b4 * w0p1sm[dy*16 + o];
        }
    }
    int aw[4];
#pragma unroll
    for (int j = 0; j < 4; j++) {
        unsigned w = 0;
#pragma unroll
        for (int b = 0; b < 4; b++)
            w |= ((unsigned)requant(acc[j*4 + b], M0)) << (8*b);
        aw[j] = (int)w;
    }
    size_t pix = (size_t)n*NPIX + (size_t)(y0 + ty)*WW + x0 + tx;
#pragma unroll
    for (int og = 0; og < 3; og++) {
        unsigned word = 0;
#pragma unroll
        for (int ob = 0; ob < 4; ob++) {
            int o = og*4 + ob;
            int a = b1sm[o];
            a = __dp4a(aw[0], w1sm[o*4 + 0], a);
            a = __dp4a(aw[1], w1sm[o*4 + 1], a);
            a = __dp4a(aw[2], w1sm[o*4 + 2], a);
            a = __dp4a(aw[3], w1sm[o*4 + 3], a);
            word |= ((unsigned)requant(a, M1)) << (8*ob);
        }
        g_pA[og*NT + pix] = (int)word;
    }
}

// ---------------- conv3x3: 12 -> 12, pad1 (layers 2..5) ----------------
// 2 output pixels per thread; out tile 64x8 per block. SoA planes in/out.
__global__ __launch_bounds__(256) void conv3_kernel(int layer,
                                                    const int* __restrict__ bias, float M)
{
    __shared__ int tile[10][3][68];   // [row][plane j][ix]; ix 0..65 valid
    __shared__ int4 wsm[108];         // [o*9+t] -> (j0, j1, j2, pad)
    __shared__ int bsm[12];
    int tid = threadIdx.y*32 + threadIdx.x;
    if (tid < 108) wsm[tid] = ((const int4*)g_w35p[layer])[tid];
    if (tid >= 128 && tid < 140) bsm[tid - 128] = bias[tid - 128];
    int flip = layer & 1;
    const int* inb = flip ? g_pB : g_pA;
    int*      outb = flip ? g_pA : g_pB;
    int n = blockIdx.z;
    int x0 = blockIdx.x*64, y0 = blockIdx.y*8;

    for (int i = tid; i < 10*3*68; i += 256) {
        int iy = i / (3*68);
        int rem = i % (3*68);
        int j = rem / 68, ix = rem % 68;
        int gy = y0 + iy - 1, gx = x0 + ix - 1;
        int v = 0;
        if (ix < 66 && gy >= 0 && gy < HH && gx >= 0 && gx < WW)
            v = inb[(size_t)j*NT + (size_t)n*NPIX + gy*WW + gx];
        tile[iy][j][ix] = v;
    }
    __syncthreads();

    int tx = threadIdx.x, ty = threadIdx.y;
    int act[3][3][4];   // [dy][j][pos], pos -> ix = 2*tx + pos
#pragma unroll
    for (int dy = 0; dy < 3; dy++)
#pragma unroll
        for (int j = 0; j < 3; j++) {
            *(int2*)&act[dy][j][0] = *(const int2*)&tile[ty + dy][j][2*tx];
            *(int2*)&act[dy][j][2] = *(const int2*)&tile[ty + dy][j][2*tx + 2];
        }

    unsigned outw[2][3];
#pragma unroll
    for (int og = 0; og < 3; og++) {
        unsigned word0 = 0, word1 = 0;
#pragma unroll
        for (int ob = 0; ob < 4; ob++) {
            int o = og*4 + ob;
            int acc0 = bsm[o];
            int acc1 = acc0;
#pragma unroll
            for (int t = 0; t < 9; t++) {
                int dy = t / 3, dx = t % 3;
                int4 w = wsm[o*9 + t];
                acc0 = __dp4a(act[dy][0][dx],     w.x, acc0);
                acc0 = __dp4a(act[dy][1][dx],     w.y, acc0);
                acc0 = __dp4a(act[dy][2][dx],     w.z, acc0);
                acc1 = __dp4a(act[dy][0][dx + 1], w.x, acc1);
                acc1 = __dp4a(act[dy][1][dx + 1], w.y, acc1);
                acc1 = __dp4a(act[dy][2][dx + 1], w.z, acc1);
            }
            word0 |= ((unsigned)requant(acc0, M)) << (8*ob);
            word1 |= ((unsigned)requant(acc1, M)) << (8*ob);
        }
        outw[0][og] = word0;
        outw[1][og] = word1;
    }
    size_t pix = (size_t)n*NPIX + (size_t)(y0 + ty)*WW + x0 + 2*tx;
#pragma unroll
    for (int j = 0; j < 3; j++)
        *(int2*)&outb[(size_t)j*NT + pix] = make_int2((int)outw[0][j], (int)outw[1][j]);
}

// ---------------- fused conv6(1x1,12->16) + deconv(16->1,k9,s4,p4) ----------------
__global__ __launch_bounds__(256) void deconv_kernel(const int* __restrict__ b6,
                                                     float M6, float out_s,
                                                     float* __restrict__ out)
{
    __shared__ float2 sin2[8][18][18];   // channel-pair j -> (c=2j, c=2j+1)
    __shared__ ulonglong2 wsm[8*41];     // g_pw2 as 16B vectors (82 float2 per j = 41)
    __shared__ int w6sm[48];
    __shared__ int b6sm[16];
    __shared__ float stile[64*64];       // output staging for coalesced store
    int tid = threadIdx.y*16 + threadIdx.x;
    for (int i = tid; i < 328; i += 256) wsm[i] = ((const ulonglong2*)g_pw2)[i];
    if (tid < 48) w6sm[tid] = g_w6p[tid];
    if (tid >= 64 && tid < 80) b6sm[tid - 64] = b6[tid - 64];
    __syncthreads();   // w6sm/b6sm needed by the tile loader below

    int n = blockIdx.z;
    int gy0 = blockIdx.y*16, gx0 = blockIdx.x*16;
    for (int u = tid; u < 324; u += 256) {
        int iy = u / 18, ix = u % 18;
        int gy = gy0 + iy - 1, gx = gx0 + ix - 1;
        if (gy >= 0 && gy < HH && gx >= 0 && gx < WW) {
            size_t base = (size_t)n*NPIX + gy*WW + gx;
            int v0 = g_pA[0*NT + base];
            int v1 = g_pA[1*NT + base];
            int v2 = g_pA[2*NT + base];
            float r[16];
#pragma unroll
            for (int o = 0; o < 16; o++) {
                int a = b6sm[o];
                a = __dp4a(v0, w6sm[o*3 + 0], a);
                a = __dp4a(v1, w6sm[o*3 + 1], a);
                a = __dp4a(v2, w6sm[o*3 + 2], a);
                r[o] = (float)requant(a, M6) * out_s;
            }
#pragma unroll
            for (int j = 0; j < 8; j++)
                sin2[j][iy][ix] = make_float2(r[2*j], r[2*j + 1]);
        } else {
#pragma unroll
            for (int j = 0; j < 8; j++)
                sin2[j][iy][ix] = make_float2(0.f, 0.f);
        }
    }
    __syncthreads();

    unsigned long long acc2[16];
#pragma unroll
    for (int i = 0; i < 16; i++) acc2[i] = 0ULL;

    for (int j = 0; j < 8; j++) {
        unsigned long long v2[9];
#pragma unroll
        for (int t = 0; t < 9; t++)
            v2[t] = *reinterpret_cast<const unsigned long long*>(
                        &sin2[j][threadIdx.y + t/3][threadIdx.x + t%3]);
        const ulonglong2* wj = &wsm[j*41];
        int seq = 0;
        ulonglong2 wpair;
#pragma unroll
        for (int ry = 0; ry < 4; ry++)
#pragma unroll
        for (int rx = 0; rx < 4; rx++) {
            const int p = ry*4 + rx;
#pragma unroll
            for (int dy = -1; dy <= 1; dy++) {
                if (dy < 0 && ry != 0) continue;
#pragma unroll
                for (int dx = -1; dx <= 1; dx++) {
                    if (dx < 0 && rx != 0) continue;
                    if ((seq & 1) == 0) wpair = wj[seq >> 1];
                    unsigned long long w = (seq & 1) ? wpair.y : wpair.x;
                    asm("fma.rn.f32x2 %0, %1, %2, %0;"
                        : "+l"(acc2[p])
                        : "l"(v2[(dy + 1)*3 + (dx + 1)]), "l"(w));
                    seq++;
                }
            }
        }
    }
    // horizontal add of channel halves + stage to smem
#pragma unroll
    for (int p = 0; p < 16; p++) {
        float lo, hi;
        asm("mov.b64 {%0, %1}, %2;" : "=f"(lo), "=f"(hi) : "l"(acc2[p]));
        stile[(threadIdx.y*4 + (p >> 2))*64 + threadIdx.x*4 + (p & 3)] = lo + hi;
    }
    __syncthreads();

    float* outn = out + (size_t)n*OD*OD;
    int oy_base = blockIdx.y*64, ox_base = blockIdx.x*64;
    for (int u = tid; u < 4096; u += 256) {
        int oyl = u >> 6, oxl = u & 63;
        int oy = oy_base + oyl, ox = ox_base + oxl;
        if (oy < OD && ox < OD)
            outn[(size_t)oy*OD + ox] = stile[u];
    }
}

// ---------------- launch ----------------
extern "C" void kernel_launch(void* const* d_in, const int* in_sizes, int n_in,
                              void* d_out, int out_size)
{
    const float* x = (const float*)d_in[0];
    const int* w[7];
    const int* b[7];
    const float* wt;
    if (in_sizes[2] == 16) {
        // interleaved: x, w0, b0, w1, b1, ..., w6, b6, wt
        for (int i = 0; i < 7; i++) {
            w[i] = (const int*)d_in[1 + 2*i];
            b[i] = (const int*)d_in[2 + 2*i];
        }
    } else {
        // grouped: x, w0..w6, b0..b6, wt
        for (int i = 0; i < 7; i++) {
            w[i] = (const int*)d_in[1 + i];
            b[i] = (const int*)d_in[8 + i];
        }
    }
    wt = (const float*)d_in[15];

    // requant multipliers: python-double products cast to f32 (matches reference scalars)
    float M0 = (float)((1.0/255.0) * 0.02 / 0.05);
    float M1 = (float)(0.05 * 0.02 / 0.04);
    float M2 = (float)(0.04 * 0.02 / 0.04);
    float M6 = (float)(0.04 * 0.02 / 0.05);

    pack_weights_kernel<<<1, 256>>>(w[0], w[1], w[2], w[3], w[4], w[5], w[6], wt);

    dim3 cblk(32, 8);
    conv01_kernel<<<dim3(WW/32, HH/8, NIMG), cblk>>>(x, b[0], b[1], M0, M1);

    dim3 c3grd(WW/64, HH/8, NIMG);
    conv3_kernel<<<c3grd, cblk>>>(0, b[2], M2);   // A -> B
    conv3_kernel<<<c3grd, cblk>>>(1, b[3], M2);   // B -> A
    conv3_kernel<<<c3grd, cblk>>>(2, b[4], M2);   // A -> B
    conv3_kernel<<<c3grd, cblk>>>(3, b[5], M2);   // B -> A

    dim3 dblk(16, 16);
    dim3 dgrd(32, 32, NIMG);
    deconv_kernel<<<dgrd, dblk>>>(b[6], M6, 0.05f, (float*)d_out);

    (void)n_in; (void)out_size;
}